// round 4
// baseline (speedup 1.0000x reference)
#include <cuda_runtime.h>
#include <math.h>

#define NROWS 1024
#define C 64
#define MARGIN_F 15.0f
#define EPSJ 1e-8f
#define HLN2 0.34657359027997264f   /* 0.5*ln2 */
#define TI 64                        /* i-tile */
#define TJ 32                        /* j-tile */
#define NBLK 512                     /* (1024/TJ)*(1024/TI) */

// ---------------- scratch (static device globals; no allocation) ----------------
__device__ float g_K[2][NROWS];      // 0.5*Sa + 0.5*ln2*sumA  per row
__device__ float g_nn[2][NROWS];     // ||x||^2 per row
__device__ float g_pos[2 * NROWS];   // per-row positive-branch contribution
__device__ float g_oodv[2 * NROWS];  // per-row ood contribution (var*coffi)
__device__ float g_rowsum[NROWS];    // negative-branch per-row pair sums
__device__ int   g_rowcnt[NROWS];    // negative-branch per-row counts (pairs > 0)
__device__ int   g_done;             // pair-kernel completion counter

__device__ __forceinline__ unsigned long long fma2(unsigned long long a,
                                                   unsigned long long b,
                                                   unsigned long long c) {
    unsigned long long d;
    asm("fma.rn.f32x2 %0, %1, %2, %3;" : "=l"(d) : "l"(a), "l"(b), "l"(c));
    return d;
}

__device__ __forceinline__ float wsum(float v) {
    #pragma unroll
    for (int off = 16; off; off >>= 1) v += __shfl_xor_sync(0xffffffffu, v, off);
    return v;
}
__device__ __forceinline__ float wmin(float v) {
    #pragma unroll
    for (int off = 16; off; off >>= 1)
        v = fminf(v, __shfl_xor_sync(0xffffffffu, v, off));
    return v;
}

// ---------------- kernel 1: warp-per-row precompute + positive + ood ------------
// One warp per (branch,row); lane handles c = lane, lane+32.
// Closed forms (one-hot structure):
//   js_j = G + h_j,  G = 1 - 0.5P - 0.5eps(C-1)ln(eps) + 0.5eps*T
//   h_j  = -0.5A_j(L0_j - L1_j) - 0.5eps*L0_j + 0.5L1_j
//   posi_row = G*sum(pd*l) + sum(pd*l*h);  pd = sqrt(max(nn - 2x_j + 1, 1e-12))
__global__ void row_kernel(const float* __restrict__ x1, const float* __restrict__ x2,
                           const float* __restrict__ xp1, const float* __restrict__ xp2,
                           const float* __restrict__ l1,  const float* __restrict__ l2) {
    int gtid = blockIdx.x * blockDim.x + threadIdx.x;
    int w    = gtid >> 5;            // warp id: 0..2047
    int lane = gtid & 31;
    if (gtid == 0) g_done = 0;
    if (gtid < NROWS) { g_rowsum[gtid] = 0.0f; g_rowcnt[gtid] = 0; }

    int br = w >> 10;
    int i  = w & (NROWS - 1);
    const float* xr = (br ? x2  : x1)  + i * C;
    const float* pr = (br ? xp2 : xp1) + i * C;
    const float* lr = (br ? l2  : l1)  + i * C;

    float xv0 = xr[lane], xv1 = xr[lane + 32];
    float A0  = pr[lane] + EPSJ, A1 = pr[lane + 32] + EPSJ;
    float lv0 = lr[lane], lv1 = lr[lane + 32];

    // phase 1: row-wide nn
    float nn = wsum(fmaf(xv0, xv0, xv1 * xv1));

    // phase 2: everything else
    float la0 = __logf(A0),                la1 = __logf(A1);
    float L00 = __logf(0.5f * (A0 + EPSJ)), L01 = __logf(0.5f * (A1 + EPSJ));
    float L10 = __logf(0.5f * (A0 + 1.0f)), L11 = __logf(0.5f * (A1 + 1.0f));
    float P  = fmaf(A0, la0 - L00, A1 * (la1 - L01));
    float T  = L00 + L01;
    float Sa = fmaf(A0, la0, A1 * la1);
    float sA = A0 + A1;

    float pd0 = sqrtf(fmaxf(nn - 2.0f * xv0 + 1.0f, 1e-12f));
    float pd1 = sqrtf(fmaxf(nn - 2.0f * xv1 + 1.0f, 1e-12f));
    float h0  = -0.5f * A0 * (L00 - L10) - 0.5f * EPSJ * L00 + 0.5f * L10;
    float h1  = -0.5f * A1 * (L01 - L11) - 0.5f * EPSJ * L01 + 0.5f * L11;
    float w0  = pd0 * lv0, w1 = pd1 * lv1;
    float S1  = w0 + w1;
    float S2  = fmaf(w0, h0, w1 * h1);
    float r0  = fmaxf(MARGIN_F - pd0, 0.0f) * (1.0f / MARGIN_F);
    float r1  = fmaxf(MARGIN_F - pd1, 0.0f) * (1.0f / MARGIN_F);
    float var = fmaf(r0, r0, r1 * r1);
    float mn  = fminf(1.0f - r0, 1.0f - r1);

    P = wsum(P); T = wsum(T); Sa = wsum(Sa); sA = wsum(sA);
    S1 = wsum(S1); S2 = wsum(S2); var = wsum(var); mn = wmin(mn);

    if (lane == 0) {
        const float LOGEPS = -18.420680743952367f;   // ln(1e-8)
        float G = 1.0f - 0.5f * P - 0.5f * EPSJ * (float)(C - 1) * LOGEPS
                       + 0.5f * EPSJ * T;
        g_pos [w]  = G * S1 + S2;
        g_oodv[w]  = var * mn;
        g_K [br][i] = 0.5f * Sa + HLN2 * sA;
        g_nn[br][i] = nn;
    }
}

// ---------------- kernel 2: pairwise negative branch + folded finalize ----------
// 64i x 32j tile per block, 16x16 threads, 4x2 register tile (i = ty+16k, j = tx+16k).
// smem stride 64 (no pad needed: all LDS are broadcast or unit-stride).
// js[i,j] = Ka[i] + Kb[j] - 0.5*ln2 * sum_c s*lg2(s),  s = A1_ic + A2_jc.
__global__ void __launch_bounds__(256, 3)
pair_kernel(const float* __restrict__ x1, const float* __restrict__ x2,
            const float* __restrict__ xp1, const float* __restrict__ xp2,
            const float* __restrict__ l1,  const float* __restrict__ l2,
            float* __restrict__ out, int out_size) {
    extern __shared__ float sm[];
    float*  sA  = sm;                         // [C][TI] xp1+eps   16 KB
    float*  sB  = sm + C * TI;                // [C][TJ] xp2+eps    8 KB
    float2* sPi = (float2*)(sm + C * (TI + TJ));        // [C][TI] (l1,x1) 32 KB
    float2* sPj = sPi + C * TI;                          // [C][TJ] (l2,x2) 16 KB
    const unsigned long long* sPi64 = (const unsigned long long*)sPi;
    const unsigned long long* sPj64 = (const unsigned long long*)sPj;

    const int tx = threadIdx.x, ty = threadIdx.y;
    const int tid = ty * 16 + tx;
    const int i0 = blockIdx.y * TI, j0 = blockIdx.x * TJ;

    #pragma unroll
    for (int t = 0; t < 4; t++) {             // 4*256 = 1024... TI*C = 4096
        int idx = tid + t * 256;
        #pragma unroll
        for (int rep = 0; rep < 4; rep++) {
            int id2 = idx + rep * 1024;
            int c = id2 & (C - 1), r = id2 >> 6;
            sA [c * TI + r] = xp1[(i0 + r) * C + c] + EPSJ;
            sPi[c * TI + r] = make_float2(l1[(i0 + r) * C + c], x1[(i0 + r) * C + c]);
        }
    }
    for (int idx = tid; idx < TJ * C; idx += 256) {
        int c = idx & (C - 1), r = idx >> 6;
        sB [c * TJ + r] = xp2[(j0 + r) * C + c] + EPSJ;
        sPj[c * TJ + r] = make_float2(l2[(j0 + r) * C + c], x2[(j0 + r) * C + c]);
    }
    __syncthreads();

    float jsum[4][2];
    unsigned long long dlx[4][2];
    #pragma unroll
    for (int a = 0; a < 4; a++)
        #pragma unroll
        for (int b = 0; b < 2; b++) { jsum[a][b] = 0.0f; dlx[a][b] = 0ull; }

    #pragma unroll 8
    for (int c = 0; c < C; c++) {
        float a[4], b[2];
        unsigned long long pi[4], pj[2];
        #pragma unroll
        for (int k = 0; k < 4; k++) {
            a [k] = sA   [c * TI + ty + 16 * k];
            pi[k] = sPi64[c * TI + ty + 16 * k];
        }
        #pragma unroll
        for (int k = 0; k < 2; k++) {
            b [k] = sB   [c * TJ + tx + 16 * k];
            pj[k] = sPj64[c * TJ + tx + 16 * k];
        }
        #pragma unroll
        for (int ki = 0; ki < 4; ki++)
            #pragma unroll
            for (int kj = 0; kj < 2; kj++) {
                float s = a[ki] + b[kj];
                float u = __log2f(s);                     // MUFU.LG2
                jsum[ki][kj] = fmaf(s, u, jsum[ki][kj]);
                dlx[ki][kj]  = fma2(pi[ki], pj[kj], dlx[ki][kj]);
            }
    }

    float Kb[2], nb[2];
    #pragma unroll
    for (int kj = 0; kj < 2; kj++) {
        int j = j0 + tx + 16 * kj;
        Kb[kj] = g_K[1][j];
        nb[kj] = g_nn[1][j];
    }

    #pragma unroll
    for (int ki = 0; ki < 4; ki++) {
        int i = i0 + ty + 16 * ki;
        float Ka = g_K[0][i];
        float na = g_nn[0][i];
        float rsum = 0.0f;
        int   rcnt = 0;
        #pragma unroll
        for (int kj = 0; kj < 2; kj++) {
            float2 v = *(float2*)&dlx[ki][kj];            // (dl, dx)
            float js = Ka + Kb[kj] - HLN2 * jsum[ki][kj];
            float d2 = fmaxf(na + nb[kj] - 2.0f * v.y, 1e-12f);
            float ed = sqrtf(d2) + 1e-10f;
            float hinge = fmaxf(MARGIN_F - ed, 0.0f);
            float pr = hinge * (1.0f - v.x) * js;
            rsum += pr;
            rcnt += (pr > 0.0f) ? 1 : 0;
        }
        #pragma unroll
        for (int off = 8; off; off >>= 1) {
            rsum += __shfl_down_sync(0xffffffffu, rsum, off, 16);
            rcnt += __shfl_down_sync(0xffffffffu, rcnt, off, 16);
        }
        if (tx == 0) {
            atomicAdd(&g_rowsum[i], rsum);
            atomicAdd(&g_rowcnt[i], rcnt);
        }
    }

    // ---- folded finalize: last block to finish reduces everything ----
    __threadfence();
    __syncthreads();
    if (tid == 0) ((int*)sm)[0] = atomicAdd(&g_done, 1);
    __syncthreads();
    int last = (((int*)sm)[0] == NBLK - 1);
    __syncthreads();
    if (!last) return;

    float nega = 0.0f, posi = 0.0f, ood = 0.0f;
    for (int r = tid; r < NROWS; r += 256) {
        float rs = __ldcg(&g_rowsum[r]);
        int   rc = __ldcg(&g_rowcnt[r]);
        nega += rs / (float)(rc > 0 ? rc : 1);
    }
    for (int r = tid; r < 2 * NROWS; r += 256) {
        posi += g_pos[r];
        ood  += g_oodv[r];
    }
    float* red = sm;
    red[tid]       = nega;
    red[256 + tid] = posi;
    red[512 + tid] = ood;
    __syncthreads();
    for (int off = 128; off; off >>= 1) {
        if (tid < off) {
            red[tid]       += red[tid + off];
            red[256 + tid] += red[256 + tid + off];
            red[512 + tid] += red[512 + tid + off];
        }
        __syncthreads();
    }
    for (int r = 3 + tid; r < out_size; r += 256) out[r] = 0.0f;  // defensive
    if (tid == 0) {
        float ng = red[0];
        float ps = 0.5f * red[256];
        float od = 0.5f * red[512];
        if (out_size > 0) out[0] = ps + ng + 0.5f * od;   // LAM = 0.5
        if (out_size > 1) out[1] = ps;
        if (out_size > 2) out[2] = ng;
    }
}

// ---------------- launch ---------------------------------------------------------
extern "C" void kernel_launch(void* const* d_in, const int* in_sizes, int n_in,
                              void* d_out, int out_size) {
    const float* x1  = (const float*)d_in[0];
    const float* x2  = (const float*)d_in[1];
    const float* xp1 = (const float*)d_in[2];
    const float* xp2 = (const float*)d_in[3];
    const float* l1  = (const float*)d_in[4];
    const float* l2  = (const float*)d_in[5];
    float* out = (float*)d_out;

    row_kernel<<<256, 256>>>(x1, x2, xp1, xp2, l1, l2);

    const int smem_bytes = (C * (TI + TJ)) * (int)sizeof(float)      // sA + sB
                         + (C * (TI + TJ)) * (int)sizeof(float2);    // sPi + sPj
    cudaFuncSetAttribute(pair_kernel, cudaFuncAttributeMaxDynamicSharedMemorySize,
                         smem_bytes);
    pair_kernel<<<dim3(NROWS / TJ, NROWS / TI), dim3(16, 16), smem_bytes>>>(
        x1, x2, xp1, xp2, l1, l2, out, out_size);
}

// round 5
// speedup vs baseline: 1.0070x; 1.0070x over previous
#include <cuda_runtime.h>
#include <math.h>

#define NROWS 1024
#define C 64
#define MARGIN_F 15.0f
#define EPSJ 1e-8f
#define HLN2 0.34657359027997264f   /* 0.5*ln2 */
#define TI 64                        /* i-tile */
#define TJ 32                        /* j-tile */
#define NBLK 512                     /* (1024/TJ)*(1024/TI) */

// ---------------- scratch (static device globals; no allocation) ----------------
__device__ float g_K[2][NROWS];      // 0.5*Sa + 0.5*ln2*sumA  per row
__device__ float g_nn[2][NROWS];     // ||x||^2 per row
__device__ float g_pos[2 * NROWS];   // per-row positive-branch contribution
__device__ float g_oodv[2 * NROWS];  // per-row ood contribution (var*coffi)
__device__ float g_rowsum[NROWS];    // negative-branch per-row pair sums
__device__ int   g_rowcnt[NROWS];    // negative-branch per-row counts
__device__ int   g_done;             // pair-kernel completion counter

__device__ __forceinline__ unsigned long long fma2(unsigned long long a,
                                                   unsigned long long b,
                                                   unsigned long long c) {
    unsigned long long d;
    asm("fma.rn.f32x2 %0, %1, %2, %3;" : "=l"(d) : "l"(a), "l"(b), "l"(c));
    return d;
}

__device__ __forceinline__ float wsum(float v) {
    #pragma unroll
    for (int off = 16; off; off >>= 1) v += __shfl_xor_sync(0xffffffffu, v, off);
    return v;
}
__device__ __forceinline__ float wmin(float v) {
    #pragma unroll
    for (int off = 16; off; off >>= 1)
        v = fminf(v, __shfl_xor_sync(0xffffffffu, v, off));
    return v;
}

// ---------------- kernel 1: warp-per-row precompute + positive + ood ------------
__global__ void row_kernel(const float* __restrict__ x1, const float* __restrict__ x2,
                           const float* __restrict__ xp1, const float* __restrict__ xp2,
                           const float* __restrict__ l1,  const float* __restrict__ l2) {
    int gtid = blockIdx.x * blockDim.x + threadIdx.x;
    int w    = gtid >> 5;            // warp id: 0..2047
    int lane = gtid & 31;
    if (gtid == 0) g_done = 0;
    if (gtid < NROWS) { g_rowsum[gtid] = 0.0f; g_rowcnt[gtid] = 0; }

    int br = w >> 10;
    int i  = w & (NROWS - 1);
    const float* xr = (br ? x2  : x1)  + i * C;
    const float* pr = (br ? xp2 : xp1) + i * C;
    const float* lr = (br ? l2  : l1)  + i * C;

    float xv0 = xr[lane], xv1 = xr[lane + 32];
    float A0  = pr[lane] + EPSJ, A1 = pr[lane + 32] + EPSJ;
    float lv0 = lr[lane], lv1 = lr[lane + 32];

    float nn = wsum(fmaf(xv0, xv0, xv1 * xv1));

    float la0 = __logf(A0),                 la1 = __logf(A1);
    float L00 = __logf(0.5f * (A0 + EPSJ)), L01 = __logf(0.5f * (A1 + EPSJ));
    float L10 = __logf(0.5f * (A0 + 1.0f)), L11 = __logf(0.5f * (A1 + 1.0f));
    float P  = fmaf(A0, la0 - L00, A1 * (la1 - L01));
    float T  = L00 + L01;
    float Sa = fmaf(A0, la0, A1 * la1);
    float sA = A0 + A1;

    float pd0 = sqrtf(fmaxf(nn - 2.0f * xv0 + 1.0f, 1e-12f));
    float pd1 = sqrtf(fmaxf(nn - 2.0f * xv1 + 1.0f, 1e-12f));
    float h0  = -0.5f * A0 * (L00 - L10) - 0.5f * EPSJ * L00 + 0.5f * L10;
    float h1  = -0.5f * A1 * (L01 - L11) - 0.5f * EPSJ * L01 + 0.5f * L11;
    float w0  = pd0 * lv0, w1 = pd1 * lv1;
    float S1  = w0 + w1;
    float S2  = fmaf(w0, h0, w1 * h1);
    float r0  = fmaxf(MARGIN_F - pd0, 0.0f) * (1.0f / MARGIN_F);
    float r1  = fmaxf(MARGIN_F - pd1, 0.0f) * (1.0f / MARGIN_F);
    float var = fmaf(r0, r0, r1 * r1);
    float mn  = fminf(1.0f - r0, 1.0f - r1);

    P = wsum(P); T = wsum(T); Sa = wsum(Sa); sA = wsum(sA);
    S1 = wsum(S1); S2 = wsum(S2); var = wsum(var); mn = wmin(mn);

    if (lane == 0) {
        const float LOGEPS = -18.420680743952367f;   // ln(1e-8)
        float G = 1.0f - 0.5f * P - 0.5f * EPSJ * (float)(C - 1) * LOGEPS
                       + 0.5f * EPSJ * T;
        g_pos [w]   = G * S1 + S2;
        g_oodv[w]   = var * mn;
        g_K [br][i] = 0.5f * Sa + HLN2 * sA;
        g_nn[br][i] = nn;
    }
}

// ---------------- kernel 2: pairwise negative branch, phase-split ---------------
// 64i x 32j tile, 16x16 threads, 4x2 register micro-tile.
// Phase A: (l,x) float2 tiles in smem (48KB) -> dl/dx grams via packed f32x2 FMA
//          -> w = hinge*(1-dl) in regs, per-row counts (w>0 <=> pairs>0 since
//          js > 0 strictly).
// Phase B: SAME smem reused for xp tiles (24KB) -> js log-sum loop
//          (FADD + MUFU.LG2 + FFMA per pair-c), pr = w*js.
// 48KB smem + <=64 regs -> 4 blocks/SM -> all 512 blocks resident, one wave.
__global__ void __launch_bounds__(256, 4)
pair_kernel(const float* __restrict__ x1, const float* __restrict__ x2,
            const float* __restrict__ xp1, const float* __restrict__ xp2,
            const float* __restrict__ l1,  const float* __restrict__ l2,
            float* __restrict__ out, int out_size) {
    extern __shared__ float sm[];
    const int tx = threadIdx.x, ty = threadIdx.y;
    const int tid = ty * 16 + tx;
    const int i0 = blockIdx.y * TI, j0 = blockIdx.x * TJ;

    float wreg[4][2];

    // ================= Phase A: grams =================
    {
        float2* sPi = (float2*)sm;            // [C][TI] (l1,x1)  32 KB
        float2* sPj = sPi + C * TI;           // [C][TJ] (l2,x2)  16 KB
        const unsigned long long* sPi64 = (const unsigned long long*)sPi;
        const unsigned long long* sPj64 = (const unsigned long long*)sPj;

        for (int idx = tid; idx < TI * C; idx += 256) {
            int c = idx & (C - 1), r = idx >> 6;
            sPi[c * TI + r] = make_float2(l1[(i0 + r) * C + c], x1[(i0 + r) * C + c]);
        }
        for (int idx = tid; idx < TJ * C; idx += 256) {
            int c = idx & (C - 1), r = idx >> 6;
            sPj[c * TJ + r] = make_float2(l2[(j0 + r) * C + c], x2[(j0 + r) * C + c]);
        }
        __syncthreads();

        unsigned long long dlx[4][2];
        #pragma unroll
        for (int a = 0; a < 4; a++)
            #pragma unroll
            for (int b = 0; b < 2; b++) dlx[a][b] = 0ull;

        #pragma unroll 4
        for (int c = 0; c < C; c++) {
            unsigned long long pi[4], pj[2];
            #pragma unroll
            for (int k = 0; k < 4; k++) pi[k] = sPi64[c * TI + ty + 16 * k];
            #pragma unroll
            for (int k = 0; k < 2; k++) pj[k] = sPj64[c * TJ + tx + 16 * k];
            #pragma unroll
            for (int ki = 0; ki < 4; ki++)
                #pragma unroll
                for (int kj = 0; kj < 2; kj++)
                    dlx[ki][kj] = fma2(pi[ki], pj[kj], dlx[ki][kj]);
        }

        float nb[2];
        #pragma unroll
        for (int kj = 0; kj < 2; kj++) nb[kj] = g_nn[1][j0 + tx + 16 * kj];

        #pragma unroll
        for (int ki = 0; ki < 4; ki++) {
            float na = g_nn[0][i0 + ty + 16 * ki];
            int rcnt = 0;
            #pragma unroll
            for (int kj = 0; kj < 2; kj++) {
                float2 v = *(float2*)&dlx[ki][kj];           // (dl, dx)
                float d2 = fmaxf(na + nb[kj] - 2.0f * v.y, 1e-12f);
                float ed = sqrtf(d2) + 1e-10f;
                float hinge = fmaxf(MARGIN_F - ed, 0.0f);
                float wv = hinge * (1.0f - v.x);
                wreg[ki][kj] = wv;
                rcnt += (wv > 0.0f) ? 1 : 0;
            }
            #pragma unroll
            for (int off = 8; off; off >>= 1)
                rcnt += __shfl_down_sync(0xffffffffu, rcnt, off, 16);
            if (tx == 0) atomicAdd(&g_rowcnt[i0 + ty + 16 * ki], rcnt);
        }
        __syncthreads();   // all reads of sPi/sPj done before overwrite
    }

    // ================= Phase B: js log-sums =================
    {
        float* sA = sm;                       // [C][TI] xp1+eps  16 KB
        float* sB = sm + C * TI;              // [C][TJ] xp2+eps   8 KB

        for (int idx = tid; idx < TI * C; idx += 256) {
            int c = idx & (C - 1), r = idx >> 6;
            sA[c * TI + r] = xp1[(i0 + r) * C + c] + EPSJ;
        }
        for (int idx = tid; idx < TJ * C; idx += 256) {
            int c = idx & (C - 1), r = idx >> 6;
            sB[c * TJ + r] = xp2[(j0 + r) * C + c] + EPSJ;
        }
        __syncthreads();

        float jsum[4][2];
        #pragma unroll
        for (int a = 0; a < 4; a++)
            #pragma unroll
            for (int b = 0; b < 2; b++) jsum[a][b] = 0.0f;

        #pragma unroll 8
        for (int c = 0; c < C; c++) {
            float a[4], b[2];
            #pragma unroll
            for (int k = 0; k < 4; k++) a[k] = sA[c * TI + ty + 16 * k];
            #pragma unroll
            for (int k = 0; k < 2; k++) b[k] = sB[c * TJ + tx + 16 * k];
            #pragma unroll
            for (int ki = 0; ki < 4; ki++)
                #pragma unroll
                for (int kj = 0; kj < 2; kj++) {
                    float s = a[ki] + b[kj];
                    jsum[ki][kj] = fmaf(s, __log2f(s), jsum[ki][kj]);
                }
        }

        float Kb[2];
        #pragma unroll
        for (int kj = 0; kj < 2; kj++) Kb[kj] = g_K[1][j0 + tx + 16 * kj];

        #pragma unroll
        for (int ki = 0; ki < 4; ki++) {
            int i = i0 + ty + 16 * ki;
            float Ka = g_K[0][i];
            float rsum = 0.0f;
            #pragma unroll
            for (int kj = 0; kj < 2; kj++) {
                float js = Ka + Kb[kj] - HLN2 * jsum[ki][kj];
                rsum = fmaf(wreg[ki][kj], js, rsum);
            }
            #pragma unroll
            for (int off = 8; off; off >>= 1)
                rsum += __shfl_down_sync(0xffffffffu, rsum, off, 16);
            if (tx == 0) atomicAdd(&g_rowsum[i], rsum);
        }
    }

    // ---- folded finalize: last block to finish reduces everything ----
    __threadfence();
    __syncthreads();
    if (tid == 0) ((int*)sm)[0] = atomicAdd(&g_done, 1);
    __syncthreads();
    int last = (((int*)sm)[0] == NBLK - 1);
    __syncthreads();
    if (!last) return;

    float nega = 0.0f, posi = 0.0f, ood = 0.0f;
    for (int r = tid; r < NROWS; r += 256) {
        float rs = __ldcg(&g_rowsum[r]);
        int   rc = __ldcg(&g_rowcnt[r]);
        nega += rs / (float)(rc > 0 ? rc : 1);
    }
    for (int r = tid; r < 2 * NROWS; r += 256) {
        posi += g_pos[r];
        ood  += g_oodv[r];
    }
    float* red = sm;
    red[tid]       = nega;
    red[256 + tid] = posi;
    red[512 + tid] = ood;
    __syncthreads();
    for (int off = 128; off; off >>= 1) {
        if (tid < off) {
            red[tid]       += red[tid + off];
            red[256 + tid] += red[256 + tid + off];
            red[512 + tid] += red[512 + tid + off];
        }
        __syncthreads();
    }
    for (int r = 3 + tid; r < out_size; r += 256) out[r] = 0.0f;  // defensive
    if (tid == 0) {
        float ng = red[0];
        float ps = 0.5f * red[256];
        float od = 0.5f * red[512];
        if (out_size > 0) out[0] = ps + ng + 0.5f * od;   // LAM = 0.5
        if (out_size > 1) out[1] = ps;
        if (out_size > 2) out[2] = ng;
    }
}

// ---------------- launch ---------------------------------------------------------
extern "C" void kernel_launch(void* const* d_in, const int* in_sizes, int n_in,
                              void* d_out, int out_size) {
    const float* x1  = (const float*)d_in[0];
    const float* x2  = (const float*)d_in[1];
    const float* xp1 = (const float*)d_in[2];
    const float* xp2 = (const float*)d_in[3];
    const float* l1  = (const float*)d_in[4];
    const float* l2  = (const float*)d_in[5];
    float* out = (float*)d_out;

    row_kernel<<<256, 256>>>(x1, x2, xp1, xp2, l1, l2);

    const int smem_bytes = C * (TI + TJ) * (int)sizeof(float2);   // 49,152 B peak
    cudaFuncSetAttribute(pair_kernel, cudaFuncAttributeMaxDynamicSharedMemorySize,
                         smem_bytes);
    pair_kernel<<<dim3(NROWS / TJ, NROWS / TI), dim3(16, 16), smem_bytes>>>(
        x1, x2, xp1, xp2, l1, l2, out, out_size);
}

// round 6
// speedup vs baseline: 1.1056x; 1.0978x over previous
#include <cuda_runtime.h>
#include <math.h>

#define NROWS 1024
#define C 64
#define MARGIN_F 15.0f
#define EPSJ 1e-8f
#define HLN2 0.34657359027997264f   /* 0.5*ln2 */
#define TI 32                        /* i-tile (rows of x1) */
#define TJ 64                        /* j-tile (rows of x2) */
#define NBLK 512                     /* (1024/TI)*(1024/TJ) */

// ---------------- scratch (static device globals; no allocation) ----------------
__device__ float g_K[2][NROWS];      // 0.5*Sa + 0.5*ln2*sumA  per row
__device__ float g_nn[2][NROWS];     // ||x||^2 per row
__device__ float g_pos[2 * NROWS];   // per-row positive-branch contribution
__device__ float g_oodv[2 * NROWS];  // per-row ood contribution (var*coffi)
__device__ float g_rowsum[NROWS];    // negative-branch per-row pair sums
__device__ int   g_rowcnt[NROWS];    // negative-branch per-row counts
__device__ int   g_done;             // pair-kernel completion counter

__device__ __forceinline__ unsigned long long fma2(unsigned long long a,
                                                   unsigned long long b,
                                                   unsigned long long c) {
    unsigned long long d;
    asm("fma.rn.f32x2 %0, %1, %2, %3;" : "=l"(d) : "l"(a), "l"(b), "l"(c));
    return d;
}

union F4U {
    float4 f;
    unsigned long long u[2];
    float s[4];
};

__device__ __forceinline__ float wsum(float v) {
    #pragma unroll
    for (int off = 16; off; off >>= 1) v += __shfl_xor_sync(0xffffffffu, v, off);
    return v;
}
__device__ __forceinline__ float wmin(float v) {
    #pragma unroll
    for (int off = 16; off; off >>= 1)
        v = fminf(v, __shfl_xor_sync(0xffffffffu, v, off));
    return v;
}

// ---------------- kernel 1: warp-per-row precompute + positive + ood ------------
__global__ void row_kernel(const float* __restrict__ x1, const float* __restrict__ x2,
                           const float* __restrict__ xp1, const float* __restrict__ xp2,
                           const float* __restrict__ l1,  const float* __restrict__ l2) {
    int gtid = blockIdx.x * blockDim.x + threadIdx.x;
    int w    = gtid >> 5;            // warp id: 0..2047
    int lane = gtid & 31;
    if (gtid == 0) g_done = 0;
    if (gtid < NROWS) { g_rowsum[gtid] = 0.0f; g_rowcnt[gtid] = 0; }

    int br = w >> 10;
    int i  = w & (NROWS - 1);
    const float* xr = (br ? x2  : x1)  + i * C;
    const float* pr = (br ? xp2 : xp1) + i * C;
    const float* lr = (br ? l2  : l1)  + i * C;

    float xv0 = xr[lane], xv1 = xr[lane + 32];
    float A0  = pr[lane] + EPSJ, A1 = pr[lane + 32] + EPSJ;
    float lv0 = lr[lane], lv1 = lr[lane + 32];

    float nn = wsum(fmaf(xv0, xv0, xv1 * xv1));

    float la0 = __logf(A0),                 la1 = __logf(A1);
    float L00 = __logf(0.5f * (A0 + EPSJ)), L01 = __logf(0.5f * (A1 + EPSJ));
    float L10 = __logf(0.5f * (A0 + 1.0f)), L11 = __logf(0.5f * (A1 + 1.0f));
    float P  = fmaf(A0, la0 - L00, A1 * (la1 - L01));
    float T  = L00 + L01;
    float Sa = fmaf(A0, la0, A1 * la1);
    float sA = A0 + A1;

    float pd0 = sqrtf(fmaxf(nn - 2.0f * xv0 + 1.0f, 1e-12f));
    float pd1 = sqrtf(fmaxf(nn - 2.0f * xv1 + 1.0f, 1e-12f));
    float h0  = -0.5f * A0 * (L00 - L10) - 0.5f * EPSJ * L00 + 0.5f * L10;
    float h1  = -0.5f * A1 * (L01 - L11) - 0.5f * EPSJ * L01 + 0.5f * L11;
    float w0  = pd0 * lv0, w1 = pd1 * lv1;
    float S1  = w0 + w1;
    float S2  = fmaf(w0, h0, w1 * h1);
    float r0  = fmaxf(MARGIN_F - pd0, 0.0f) * (1.0f / MARGIN_F);
    float r1  = fmaxf(MARGIN_F - pd1, 0.0f) * (1.0f / MARGIN_F);
    float var = fmaf(r0, r0, r1 * r1);
    float mn  = fminf(1.0f - r0, 1.0f - r1);

    P = wsum(P); T = wsum(T); Sa = wsum(Sa); sA = wsum(sA);
    S1 = wsum(S1); S2 = wsum(S2); var = wsum(var); mn = wmin(mn);

    if (lane == 0) {
        const float LOGEPS = -18.420680743952367f;   // ln(1e-8)
        float G = 1.0f - 0.5f * P - 0.5f * EPSJ * (float)(C - 1) * LOGEPS
                       + 0.5f * EPSJ * T;
        g_pos [w]   = G * S1 + S2;
        g_oodv[w]   = var * mn;
        g_K [br][i] = 0.5f * Sa + HLN2 * sA;
        g_nn[br][i] = nn;
    }
}

// ---------------- kernel 2: pairwise negative branch, phase-split ---------------
// 32i x 64j tile, 256 threads (16tx x 16ty), micro-tile 2i x 4j CONTIGUOUS:
//   i = i0 + ty*2 + ki, j = j0 + tx*4 + kj  -> all smem reads vectorized.
// Phase A (grams, 48KB smem): per c-iter: 1 LDS.128 (pi, broadcast) +
//   2 LDS.128 (pj) + 8 packed f32x2 FMA. Then w = hinge*(1-dl), counts.
// Phase B (js, 24KB smem, reused): per c-iter: LDS.64 (a) + LDS.128 (b) +
//   8 x (FADD + MUFU.LG2 + FFMA).  js = Ka + Kb - 0.5ln2 * sum s*lg2(s).
// 48KB + <=64 regs -> 4 blocks/SM -> all 512 blocks resident in one wave.
__global__ void __launch_bounds__(256, 4)
pair_kernel(const float* __restrict__ x1, const float* __restrict__ x2,
            const float* __restrict__ xp1, const float* __restrict__ xp2,
            const float* __restrict__ l1,  const float* __restrict__ l2,
            float* __restrict__ out, int out_size) {
    extern __shared__ float sm[];
    const int tx = threadIdx.x, ty = threadIdx.y;
    const int tid = ty * 16 + tx;
    const int i0 = blockIdx.y * TI, j0 = blockIdx.x * TJ;

    float wreg[2][4];

    // ================= Phase A: grams =================
    {
        float2* sPi = (float2*)sm;            // [C][TI] (l1,x1)  16 KB
        float2* sPj = sPi + C * TI;           // [C][TJ] (l2,x2)  32 KB

        // stage i-side: lanes row-major -> STS banks 2-way at worst
        {
            int r = tid & 31, c0 = tid >> 5;          // c0: 0..7
            #pragma unroll
            for (int p = 0; p < 2; p++) {
                int cb = c0 + 8 * p;                  // 4-col block 0..15
                float4 lv = *(const float4*)&l1[(i0 + r) * C + cb * 4];
                float4 xv = *(const float4*)&x1[(i0 + r) * C + cb * 4];
                sPi[(cb * 4 + 0) * TI + r] = make_float2(lv.x, xv.x);
                sPi[(cb * 4 + 1) * TI + r] = make_float2(lv.y, xv.y);
                sPi[(cb * 4 + 2) * TI + r] = make_float2(lv.z, xv.z);
                sPi[(cb * 4 + 3) * TI + r] = make_float2(lv.w, xv.w);
            }
        }
        // stage j-side
        {
            int r = tid & 63, c0 = tid >> 6;          // c0: 0..3
            #pragma unroll
            for (int p = 0; p < 4; p++) {
                int cb = c0 + 4 * p;                  // 0..15
                float4 lv = *(const float4*)&l2[(j0 + r) * C + cb * 4];
                float4 xv = *(const float4*)&x2[(j0 + r) * C + cb * 4];
                sPj[(cb * 4 + 0) * TJ + r] = make_float2(lv.x, xv.x);
                sPj[(cb * 4 + 1) * TJ + r] = make_float2(lv.y, xv.y);
                sPj[(cb * 4 + 2) * TJ + r] = make_float2(lv.z, xv.z);
                sPj[(cb * 4 + 3) * TJ + r] = make_float2(lv.w, xv.w);
            }
        }
        __syncthreads();

        unsigned long long dlx[2][4];
        #pragma unroll
        for (int a = 0; a < 2; a++)
            #pragma unroll
            for (int b = 0; b < 4; b++) dlx[a][b] = 0ull;

        const float4* pi4 = (const float4*)sPi + ty;        // stride TI/2=16 per c
        const float4* pj4 = (const float4*)sPj + tx * 2;    // stride TJ/2=32 per c

        #pragma unroll 8
        for (int c = 0; c < C; c++) {
            F4U pi, pj0, pj1;
            pi.f  = pi4[c * (TI / 2)];
            pj0.f = pj4[c * (TJ / 2)];
            pj1.f = pj4[c * (TJ / 2) + 1];
            unsigned long long pj[4] = {pj0.u[0], pj0.u[1], pj1.u[0], pj1.u[1]};
            #pragma unroll
            for (int ki = 0; ki < 2; ki++)
                #pragma unroll
                for (int kj = 0; kj < 4; kj++)
                    dlx[ki][kj] = fma2(pi.u[ki], pj[kj], dlx[ki][kj]);
        }

        F4U nb;
        nb.f = *(const float4*)&g_nn[1][j0 + tx * 4];

        #pragma unroll
        for (int ki = 0; ki < 2; ki++) {
            float na = g_nn[0][i0 + ty * 2 + ki];
            int rcnt = 0;
            #pragma unroll
            for (int kj = 0; kj < 4; kj++) {
                float2 v = *(float2*)&dlx[ki][kj];           // (dl, dx)
                float d2 = fmaxf(na + nb.s[kj] - 2.0f * v.y, 1e-12f);
                float ed = sqrtf(d2) + 1e-10f;
                float hinge = fmaxf(MARGIN_F - ed, 0.0f);
                float wv = hinge * (1.0f - v.x);             // >0 <=> pair counted
                wreg[ki][kj] = wv;
                rcnt += (wv > 0.0f) ? 1 : 0;
            }
            #pragma unroll
            for (int off = 8; off; off >>= 1)
                rcnt += __shfl_down_sync(0xffffffffu, rcnt, off, 16);
            if (tx == 0) atomicAdd(&g_rowcnt[i0 + ty * 2 + ki], rcnt);
        }
        __syncthreads();   // all reads of sPi/sPj done before overwrite
    }

    // ================= Phase B: js log-sums =================
    {
        float* sA = sm;                       // [C][TI] xp1+eps   8 KB
        float* sB = sm + C * TI;              // [C][TJ] xp2+eps  16 KB

        {
            int r = tid & 31, c0 = tid >> 5;
            #pragma unroll
            for (int p = 0; p < 2; p++) {
                int cb = c0 + 8 * p;
                float4 v = *(const float4*)&xp1[(i0 + r) * C + cb * 4];
                sA[(cb * 4 + 0) * TI + r] = v.x + EPSJ;   // banks = r -> conflict-free
                sA[(cb * 4 + 1) * TI + r] = v.y + EPSJ;
                sA[(cb * 4 + 2) * TI + r] = v.z + EPSJ;
                sA[(cb * 4 + 3) * TI + r] = v.w + EPSJ;
            }
        }
        {
            int r = tid & 63, c0 = tid >> 6;
            #pragma unroll
            for (int p = 0; p < 4; p++) {
                int cb = c0 + 4 * p;
                float4 v = *(const float4*)&xp2[(j0 + r) * C + cb * 4];
                sB[(cb * 4 + 0) * TJ + r] = v.x + EPSJ;
                sB[(cb * 4 + 1) * TJ + r] = v.y + EPSJ;
                sB[(cb * 4 + 2) * TJ + r] = v.z + EPSJ;
                sB[(cb * 4 + 3) * TJ + r] = v.w + EPSJ;
            }
        }
        __syncthreads();

        float jsum[2][4];
        #pragma unroll
        for (int a = 0; a < 2; a++)
            #pragma unroll
            for (int b = 0; b < 4; b++) jsum[a][b] = 0.0f;

        const float2* a2 = (const float2*)sA + ty;      // stride TI/2=16 per c
        const float4* b4 = (const float4*)sB + tx;      // stride TJ/4=16 per c

        #pragma unroll 8
        for (int c = 0; c < C; c++) {
            float2 av = a2[c * (TI / 2)];
            F4U bv; bv.f = b4[c * (TJ / 4)];
            float a[2] = {av.x, av.y};
            #pragma unroll
            for (int ki = 0; ki < 2; ki++)
                #pragma unroll
                for (int kj = 0; kj < 4; kj++) {
                    float s = a[ki] + bv.s[kj];
                    jsum[ki][kj] = fmaf(s, __log2f(s), jsum[ki][kj]);
                }
        }

        F4U Kb;
        Kb.f = *(const float4*)&g_K[1][j0 + tx * 4];

        #pragma unroll
        for (int ki = 0; ki < 2; ki++) {
            int i = i0 + ty * 2 + ki;
            float Ka = g_K[0][i];
            float rsum = 0.0f;
            #pragma unroll
            for (int kj = 0; kj < 4; kj++) {
                float js = Ka + Kb.s[kj] - HLN2 * jsum[ki][kj];
                rsum = fmaf(wreg[ki][kj], js, rsum);
            }
            #pragma unroll
            for (int off = 8; off; off >>= 1)
                rsum += __shfl_down_sync(0xffffffffu, rsum, off, 16);
            if (tx == 0) atomicAdd(&g_rowsum[i], rsum);
        }
    }

    // ---- folded finalize: last block to finish reduces everything ----
    __threadfence();
    __syncthreads();
    if (tid == 0) ((int*)sm)[0] = atomicAdd(&g_done, 1);
    __syncthreads();
    int last = (((int*)sm)[0] == NBLK - 1);
    __syncthreads();
    if (!last) return;

    float nega = 0.0f, posi = 0.0f, ood = 0.0f;
    for (int r = tid; r < NROWS; r += 256) {
        float rs = __ldcg(&g_rowsum[r]);
        int   rc = __ldcg(&g_rowcnt[r]);
        nega += rs / (float)(rc > 0 ? rc : 1);
    }
    for (int r = tid; r < 2 * NROWS; r += 256) {
        posi += g_pos[r];
        ood  += g_oodv[r];
    }
    float* red = sm;
    red[tid]       = nega;
    red[256 + tid] = posi;
    red[512 + tid] = ood;
    __syncthreads();
    for (int off = 128; off; off >>= 1) {
        if (tid < off) {
            red[tid]       += red[tid + off];
            red[256 + tid] += red[256 + tid + off];
            red[512 + tid] += red[512 + tid + off];
        }
        __syncthreads();
    }
    for (int r = 3 + tid; r < out_size; r += 256) out[r] = 0.0f;  // defensive
    if (tid == 0) {
        float ng = red[0];
        float ps = 0.5f * red[256];
        float od = 0.5f * red[512];
        if (out_size > 0) out[0] = ps + ng + 0.5f * od;   // LAM = 0.5
        if (out_size > 1) out[1] = ps;
        if (out_size > 2) out[2] = ng;
    }
}

// ---------------- launch ---------------------------------------------------------
extern "C" void kernel_launch(void* const* d_in, const int* in_sizes, int n_in,
                              void* d_out, int out_size) {
    const float* x1  = (const float*)d_in[0];
    const float* x2  = (const float*)d_in[1];
    const float* xp1 = (const float*)d_in[2];
    const float* xp2 = (const float*)d_in[3];
    const float* l1  = (const float*)d_in[4];
    const float* l2  = (const float*)d_in[5];
    float* out = (float*)d_out;

    row_kernel<<<256, 256>>>(x1, x2, xp1, xp2, l1, l2);

    const int smem_bytes = C * (TI + TJ) * (int)sizeof(float2);   // 49,152 B peak
    cudaFuncSetAttribute(pair_kernel, cudaFuncAttributeMaxDynamicSharedMemorySize,
                         smem_bytes);
    pair_kernel<<<dim3(NROWS / TJ, NROWS / TI), dim3(16, 16), smem_bytes>>>(
        x1, x2, xp1, xp2, l1, l2, out, out_size);
}

// round 7
// speedup vs baseline: 1.1567x; 1.0463x over previous
#include <cuda_runtime.h>
#include <math.h>

#define NROWS 1024
#define C 64
#define MARGIN_F 15.0f
#define EPSJ 1e-8f
#define HLN2 0.34657359027997264f   /* 0.5*ln2 */
#define TI 32                        /* i-tile (rows of x1) */
#define TJ 64                        /* j-tile (rows of x2) */
#define NBLK 512                     /* (1024/TI)*(1024/TJ) */
#define NTHR 128                     /* threads per block (16x8) */

// ---------------- scratch (static device globals; no allocation) ----------------
__device__ float g_K[2][NROWS];      // 0.5*Sa + 0.5*ln2*sumA  per row
__device__ float g_nn[2][NROWS];     // ||x||^2 per row
__device__ float g_pos[2 * NROWS];   // per-row positive-branch contribution
__device__ float g_oodv[2 * NROWS];  // per-row ood contribution (var*coffi)
__device__ float g_rowsum[NROWS];    // negative-branch per-row pair sums
__device__ int   g_rowcnt[NROWS];    // negative-branch per-row counts
__device__ int   g_done;             // pair-kernel completion counter

__device__ __forceinline__ unsigned long long fma2(unsigned long long a,
                                                   unsigned long long b,
                                                   unsigned long long c) {
    unsigned long long d;
    asm("fma.rn.f32x2 %0, %1, %2, %3;" : "=l"(d) : "l"(a), "l"(b), "l"(c));
    return d;
}

union F4U {
    float4 f;
    unsigned long long u[2];
    float s[4];
};

__device__ __forceinline__ float wsum(float v) {
    #pragma unroll
    for (int off = 16; off; off >>= 1) v += __shfl_xor_sync(0xffffffffu, v, off);
    return v;
}
__device__ __forceinline__ float wmin(float v) {
    #pragma unroll
    for (int off = 16; off; off >>= 1)
        v = fminf(v, __shfl_xor_sync(0xffffffffu, v, off));
    return v;
}

// ---------------- kernel 1: warp-per-row precompute + positive + ood ------------
__global__ void row_kernel(const float* __restrict__ x1, const float* __restrict__ x2,
                           const float* __restrict__ xp1, const float* __restrict__ xp2,
                           const float* __restrict__ l1,  const float* __restrict__ l2) {
    int gtid = blockIdx.x * blockDim.x + threadIdx.x;
    int w    = gtid >> 5;            // warp id: 0..2047
    int lane = gtid & 31;
    if (gtid == 0) g_done = 0;
    if (gtid < NROWS) { g_rowsum[gtid] = 0.0f; g_rowcnt[gtid] = 0; }

    int br = w >> 10;
    int i  = w & (NROWS - 1);
    const float* xr = (br ? x2  : x1)  + i * C;
    const float* pr = (br ? xp2 : xp1) + i * C;
    const float* lr = (br ? l2  : l1)  + i * C;

    float xv0 = xr[lane], xv1 = xr[lane + 32];
    float A0  = pr[lane] + EPSJ, A1 = pr[lane + 32] + EPSJ;
    float lv0 = lr[lane], lv1 = lr[lane + 32];

    float nn = wsum(fmaf(xv0, xv0, xv1 * xv1));

    float la0 = __logf(A0),                 la1 = __logf(A1);
    float L00 = __logf(0.5f * (A0 + EPSJ)), L01 = __logf(0.5f * (A1 + EPSJ));
    float L10 = __logf(0.5f * (A0 + 1.0f)), L11 = __logf(0.5f * (A1 + 1.0f));
    float P  = fmaf(A0, la0 - L00, A1 * (la1 - L01));
    float T  = L00 + L01;
    float Sa = fmaf(A0, la0, A1 * la1);
    float sA = A0 + A1;

    float pd0 = sqrtf(fmaxf(nn - 2.0f * xv0 + 1.0f, 1e-12f));
    float pd1 = sqrtf(fmaxf(nn - 2.0f * xv1 + 1.0f, 1e-12f));
    float h0  = -0.5f * A0 * (L00 - L10) - 0.5f * EPSJ * L00 + 0.5f * L10;
    float h1  = -0.5f * A1 * (L01 - L11) - 0.5f * EPSJ * L01 + 0.5f * L11;
    float w0  = pd0 * lv0, w1 = pd1 * lv1;
    float S1  = w0 + w1;
    float S2  = fmaf(w0, h0, w1 * h1);
    float r0  = fmaxf(MARGIN_F - pd0, 0.0f) * (1.0f / MARGIN_F);
    float r1  = fmaxf(MARGIN_F - pd1, 0.0f) * (1.0f / MARGIN_F);
    float var = fmaf(r0, r0, r1 * r1);
    float mn  = fminf(1.0f - r0, 1.0f - r1);

    P = wsum(P); T = wsum(T); Sa = wsum(Sa); sA = wsum(sA);
    S1 = wsum(S1); S2 = wsum(S2); var = wsum(var); mn = wmin(mn);

    if (lane == 0) {
        const float LOGEPS = -18.420680743952367f;   // ln(1e-8)
        float G = 1.0f - 0.5f * P - 0.5f * EPSJ * (float)(C - 1) * LOGEPS
                       + 0.5f * EPSJ * T;
        g_pos [w]   = G * S1 + S2;
        g_oodv[w]   = var * mn;
        g_K [br][i] = 0.5f * Sa + HLN2 * sA;
        g_nn[br][i] = nn;
    }
}

// ---------------- kernel 2: pairwise negative branch, phase-split ---------------
// 32i x 64j tile, 128 threads (16tx x 8ty), micro-tile 4i x 4j CONTIGUOUS:
//   i = i0 + ty*4 + ki,  j = j0 + tx*4 + kj.
// Phase A (grams, 48KB): per c-iter: 4x LDS.128 + 16 packed f32x2 FMA -> 16 pairs.
//   -> w = hinge*(1-dl) regs, per-row counts (w>0 <=> pairs>0, js>0 strictly).
// Phase B (js, 24KB reused): per c-iter: 2x LDS.128 + 16x(FADD+MUFU.LG2+FFMA).
//   js = Ka + Kb - 0.5ln2 * sum_c s*lg2(s),  s = A1_ic + A2_jc.
// smem bytes/pair: 4 + 2 (was 6 + 3) -> crossbar demand ~21k cyc/SM.
// 48KB + 4 blocks/SM -> all 512 blocks resident in one wave.
__global__ void __launch_bounds__(NTHR, 4)
pair_kernel(const float* __restrict__ x1, const float* __restrict__ x2,
            const float* __restrict__ xp1, const float* __restrict__ xp2,
            const float* __restrict__ l1,  const float* __restrict__ l2,
            float* __restrict__ out, int out_size) {
    extern __shared__ float sm[];
    const int tx = threadIdx.x, ty = threadIdx.y;
    const int tid = ty * 16 + tx;
    const int i0 = blockIdx.y * TI, j0 = blockIdx.x * TJ;

    float wreg[4][4];

    // ================= Phase A: grams =================
    {
        float2* sPi = (float2*)sm;            // [C][TI] (l1,x1)  16 KB
        float2* sPj = sPi + C * TI;           // [C][TJ] (l2,x2)  32 KB

        // stage i-side (32 rows x 16 col-blocks)
        {
            int r = tid & 31, c0 = tid >> 5;          // c0: 0..3
            #pragma unroll
            for (int p = 0; p < 4; p++) {
                int cb = c0 + 4 * p;                  // 0..15
                float4 lv = *(const float4*)&l1[(i0 + r) * C + cb * 4];
                float4 xv = *(const float4*)&x1[(i0 + r) * C + cb * 4];
                sPi[(cb * 4 + 0) * TI + r] = make_float2(lv.x, xv.x);
                sPi[(cb * 4 + 1) * TI + r] = make_float2(lv.y, xv.y);
                sPi[(cb * 4 + 2) * TI + r] = make_float2(lv.z, xv.z);
                sPi[(cb * 4 + 3) * TI + r] = make_float2(lv.w, xv.w);
            }
        }
        // stage j-side (64 rows x 16 col-blocks)
        {
            int r = tid & 63, c0 = tid >> 6;          // c0: 0..1
            #pragma unroll
            for (int p = 0; p < 8; p++) {
                int cb = c0 + 2 * p;                  // 0..15
                float4 lv = *(const float4*)&l2[(j0 + r) * C + cb * 4];
                float4 xv = *(const float4*)&x2[(j0 + r) * C + cb * 4];
                sPj[(cb * 4 + 0) * TJ + r] = make_float2(lv.x, xv.x);
                sPj[(cb * 4 + 1) * TJ + r] = make_float2(lv.y, xv.y);
                sPj[(cb * 4 + 2) * TJ + r] = make_float2(lv.z, xv.z);
                sPj[(cb * 4 + 3) * TJ + r] = make_float2(lv.w, xv.w);
            }
        }
        __syncthreads();

        unsigned long long dlx[4][4];
        #pragma unroll
        for (int a = 0; a < 4; a++)
            #pragma unroll
            for (int b = 0; b < 4; b++) dlx[a][b] = 0ull;

        const float4* pi4 = (const float4*)sPi + ty * 2;    // 2 f4 / thread, stride 16/c
        const float4* pj4 = (const float4*)sPj + tx * 2;    // 2 f4 / thread, stride 32/c

        #pragma unroll 4
        for (int c = 0; c < C; c++) {
            F4U pia, pib, pja, pjb;
            pia.f = pi4[c * (TI / 2)];
            pib.f = pi4[c * (TI / 2) + 1];
            pja.f = pj4[c * (TJ / 2)];
            pjb.f = pj4[c * (TJ / 2) + 1];
            unsigned long long pi[4] = {pia.u[0], pia.u[1], pib.u[0], pib.u[1]};
            unsigned long long pj[4] = {pja.u[0], pja.u[1], pjb.u[0], pjb.u[1]};
            #pragma unroll
            for (int ki = 0; ki < 4; ki++)
                #pragma unroll
                for (int kj = 0; kj < 4; kj++)
                    dlx[ki][kj] = fma2(pi[ki], pj[kj], dlx[ki][kj]);
        }

        F4U nb, na;
        nb.f = *(const float4*)&g_nn[1][j0 + tx * 4];
        na.f = *(const float4*)&g_nn[0][i0 + ty * 4];

        #pragma unroll
        for (int ki = 0; ki < 4; ki++) {
            int rcnt = 0;
            #pragma unroll
            for (int kj = 0; kj < 4; kj++) {
                float2 v = *(float2*)&dlx[ki][kj];           // (dl, dx)
                float d2 = fmaxf(na.s[ki] + nb.s[kj] - 2.0f * v.y, 1e-12f);
                float ed = sqrtf(d2) + 1e-10f;
                float hinge = fmaxf(MARGIN_F - ed, 0.0f);
                float wv = hinge * (1.0f - v.x);             // >0 <=> pair counted
                wreg[ki][kj] = wv;
                rcnt += (wv > 0.0f) ? 1 : 0;
            }
            #pragma unroll
            for (int off = 8; off; off >>= 1)
                rcnt += __shfl_down_sync(0xffffffffu, rcnt, off, 16);
            if (tx == 0) atomicAdd(&g_rowcnt[i0 + ty * 4 + ki], rcnt);
        }
        __syncthreads();   // all reads of sPi/sPj done before overwrite
    }

    // ================= Phase B: js log-sums =================
    {
        float* sA = sm;                       // [C][TI] xp1+eps   8 KB
        float* sB = sm + C * TI;              // [C][TJ] xp2+eps  16 KB

        {
            int r = tid & 31, c0 = tid >> 5;
            #pragma unroll
            for (int p = 0; p < 4; p++) {
                int cb = c0 + 4 * p;
                float4 v = *(const float4*)&xp1[(i0 + r) * C + cb * 4];
                sA[(cb * 4 + 0) * TI + r] = v.x + EPSJ;
                sA[(cb * 4 + 1) * TI + r] = v.y + EPSJ;
                sA[(cb * 4 + 2) * TI + r] = v.z + EPSJ;
                sA[(cb * 4 + 3) * TI + r] = v.w + EPSJ;
            }
        }
        {
            int r = tid & 63, c0 = tid >> 6;
            #pragma unroll
            for (int p = 0; p < 8; p++) {
                int cb = c0 + 2 * p;
                float4 v = *(const float4*)&xp2[(j0 + r) * C + cb * 4];
                sB[(cb * 4 + 0) * TJ + r] = v.x + EPSJ;
                sB[(cb * 4 + 1) * TJ + r] = v.y + EPSJ;
                sB[(cb * 4 + 2) * TJ + r] = v.z + EPSJ;
                sB[(cb * 4 + 3) * TJ + r] = v.w + EPSJ;
            }
        }
        __syncthreads();

        float jsum[4][4];
        #pragma unroll
        for (int a = 0; a < 4; a++)
            #pragma unroll
            for (int b = 0; b < 4; b++) jsum[a][b] = 0.0f;

        const float4* a4 = (const float4*)sA + ty;      // stride TI/4=8 per c
        const float4* b4 = (const float4*)sB + tx;      // stride TJ/4=16 per c

        #pragma unroll 4
        for (int c = 0; c < C; c++) {
            F4U av, bv;
            av.f = a4[c * (TI / 4)];
            bv.f = b4[c * (TJ / 4)];
            #pragma unroll
            for (int ki = 0; ki < 4; ki++)
                #pragma unroll
                for (int kj = 0; kj < 4; kj++) {
                    float s = av.s[ki] + bv.s[kj];
                    jsum[ki][kj] = fmaf(s, __log2f(s), jsum[ki][kj]);
                }
        }

        F4U Kb, Ka;
        Kb.f = *(const float4*)&g_K[1][j0 + tx * 4];
        Ka.f = *(const float4*)&g_K[0][i0 + ty * 4];

        #pragma unroll
        for (int ki = 0; ki < 4; ki++) {
            int i = i0 + ty * 4 + ki;
            float rsum = 0.0f;
            #pragma unroll
            for (int kj = 0; kj < 4; kj++) {
                float js = Ka.s[ki] + Kb.s[kj] - HLN2 * jsum[ki][kj];
                rsum = fmaf(wreg[ki][kj], js, rsum);
            }
            #pragma unroll
            for (int off = 8; off; off >>= 1)
                rsum += __shfl_down_sync(0xffffffffu, rsum, off, 16);
            if (tx == 0) atomicAdd(&g_rowsum[i], rsum);
        }
    }

    // ---- folded finalize: last block to finish reduces everything ----
    __threadfence();
    __syncthreads();
    if (tid == 0) ((int*)sm)[0] = atomicAdd(&g_done, 1);
    __syncthreads();
    int last = (((int*)sm)[0] == NBLK - 1);
    __syncthreads();
    if (!last) return;

    float nega = 0.0f, posi = 0.0f, ood = 0.0f;
    for (int r = tid; r < NROWS; r += NTHR) {
        float rs = __ldcg(&g_rowsum[r]);
        int   rc = __ldcg(&g_rowcnt[r]);
        nega += rs / (float)(rc > 0 ? rc : 1);
    }
    for (int r = tid; r < 2 * NROWS; r += NTHR) {
        posi += g_pos[r];
        ood  += g_oodv[r];
    }
    float* red = sm;
    red[tid]            = nega;
    red[NTHR + tid]     = posi;
    red[2 * NTHR + tid] = ood;
    __syncthreads();
    for (int off = NTHR / 2; off; off >>= 1) {
        if (tid < off) {
            red[tid]            += red[tid + off];
            red[NTHR + tid]     += red[NTHR + tid + off];
            red[2 * NTHR + tid] += red[2 * NTHR + tid + off];
        }
        __syncthreads();
    }
    for (int r = 3 + tid; r < out_size; r += NTHR) out[r] = 0.0f;  // defensive
    if (tid == 0) {
        float ng = red[0];
        float ps = 0.5f * red[NTHR];
        float od = 0.5f * red[2 * NTHR];
        if (out_size > 0) out[0] = ps + ng + 0.5f * od;   // LAM = 0.5
        if (out_size > 1) out[1] = ps;
        if (out_size > 2) out[2] = ng;
    }
}

// ---------------- launch ---------------------------------------------------------
extern "C" void kernel_launch(void* const* d_in, const int* in_sizes, int n_in,
                              void* d_out, int out_size) {
    const float* x1  = (const float*)d_in[0];
    const float* x2  = (const float*)d_in[1];
    const float* xp1 = (const float*)d_in[2];
    const float* xp2 = (const float*)d_in[3];
    const float* l1  = (const float*)d_in[4];
    const float* l2  = (const float*)d_in[5];
    float* out = (float*)d_out;

    row_kernel<<<256, 256>>>(x1, x2, xp1, xp2, l1, l2);

    const int smem_bytes = C * (TI + TJ) * (int)sizeof(float2);   // 49,152 B peak
    cudaFuncSetAttribute(pair_kernel, cudaFuncAttributeMaxDynamicSharedMemorySize,
                         smem_bytes);
    pair_kernel<<<dim3(NROWS / TJ, NROWS / TI), dim3(16, 8), smem_bytes>>>(
        x1, x2, xp1, xp2, l1, l2, out, out_size);
}